// round 7
// baseline (speedup 1.0000x reference)
#include <cuda_runtime.h>
#include <cuda_bf16.h>
#include <cstdint>

// Problem constants
#define N_NODES 50000
#define N_EDGES 800000
#define D_IN    128
#define D_HID   256
#define D_OUT   128

// ---------------- scratch (static device globals; no allocation) -------------
// NOTE: these symbols must ONLY be referenced from device code. Passing them
// as kernel arguments from host code yields the host shadow address, which on
// GB300 (HMM/ATS) is silently dereferenceable -> wrong results, no fault.
__device__ int   g_is64;                           // edge_index dtype flag
__device__ float g_deg [N_NODES];
__device__ float g_agg1[(size_t)N_NODES * D_IN];   // sum of x over in-edges
__device__ float g_h   [(size_t)N_NODES * D_HID];  // layer-1 output
__device__ float g_p   [(size_t)N_NODES * D_OUT];  // h @ W_l2^T (pre-aggregation)
__device__ float g_agg2[(size_t)N_NODES * D_OUT];  // sum of p over in-edges

// ---------------- dtype detect: int64 vs int32 edge_index --------------------
// Reinterpret the first 4096 entries as int64. If the data is really int32,
// each int64 view combines two indices (lo + hi*2^32) and is >= 2^32 unless
// the odd-position index is exactly 0 — vanishing probability over 4096
// samples. Deterministic given fixed inputs.
__global__ void detect_kernel(const long long* __restrict__ ei64) {
    __shared__ int bad;
    if (threadIdx.x == 0) bad = 0;
    __syncthreads();
    for (int i = threadIdx.x; i < 4096; i += blockDim.x) {
        long long v = ei64[i];
        if (v < 0 || v >= N_NODES) bad = 1;
    }
    __syncthreads();
    if (threadIdx.x == 0) g_is64 = bad ? 0 : 1;
}

// ---------------- zero scratch ----------------------------------------------
__global__ void zero_kernel() {
    int i = blockIdx.x * blockDim.x + threadIdx.x;
    const int n4a = N_NODES * D_IN  / 4;   // 1.6M
    const int n4b = N_NODES * D_OUT / 4;   // 1.6M
    float4 z = make_float4(0.f, 0.f, 0.f, 0.f);
    if (i < n4a) reinterpret_cast<float4*>(g_agg1)[i] = z;
    if (i < n4b) reinterpret_cast<float4*>(g_agg2)[i] = z;
    if (i < N_NODES) g_deg[i] = 0.f;
}

// ---------------- edge scatter (gather feat[src], red-add into agg[dst]) ----
// PASS 1: feat = x (kernel arg), agg = g_agg1 (device symbol), counts degree.
// PASS 2: feat = g_p, agg = g_agg2 (both device symbols, referenced in-kernel).
// One warp handles EPW edges; each lane handles one float4 (32 lanes * 4 = 128).
// REDG is no-return, so EPW independent v4-reductions per lane give free MLP.
#define EPW 4
template <int PASS>
__global__ __launch_bounds__(256) void edge_scatter(
        const float* __restrict__ xin,
        const void* __restrict__ ei_raw) {
    const int warp  = (blockIdx.x * blockDim.x + threadIdx.x) >> 5;
    const int lane  = threadIdx.x & 31;
    const int ebase = warp * EPW;
    if (ebase >= N_EDGES) return;

    const float* feat = (PASS == 1) ? xin : g_p;      // device-side symbol ref
    float*       agg  = (PASS == 1) ? g_agg1 : g_agg2;

    const int is64 = g_is64;   // uniform branch, read once
    const int*       ei32 = (const int*)ei_raw;
    const long long* ei64 = (const long long*)ei_raw;

    #pragma unroll
    for (int q = 0; q < EPW; q++) {
        int e = ebase + q;
        if (e >= N_EDGES) break;
        int src, dst;
        if (is64) {
            src = (int)__ldg(&ei64[e]);
            dst = (int)__ldg(&ei64[N_EDGES + e]);
        } else {
            src = __ldg(&ei32[e]);
            dst = __ldg(&ei32[N_EDGES + e]);
        }

        float4 v = __ldg(reinterpret_cast<const float4*>(
                             feat + (size_t)src * 128) + lane);
        float* p = agg + (size_t)dst * 128 + lane * 4;
        asm volatile("red.global.add.v4.f32 [%0], {%1,%2,%3,%4};"
                     :: "l"(p), "f"(v.x), "f"(v.y), "f"(v.z), "f"(v.w)
                     : "memory");
        if (PASS == 1 && lane == 0) {
            asm volatile("red.global.add.f32 [%0], %1;"
                         :: "l"(&g_deg[dst]), "f"(1.0f) : "memory");
        }
    }
}

// ---------------- tiled fp32 GEMM -------------------------------------------
#define BM 64
#define BN 128
#define BK 32
#define TM 8
#define TN 4
// 256 threads: 8 thread-rows (TM=8) x 32 thread-cols (TN=4)

// Layer 1: h[i, 0:256] = (agg1[i]/max(deg,1)) @ W_l1^T + b_l1 + x[i] @ W_r1^T
// Single GEMM, K=256: k<128 -> normalized agg1 vs W_l1 ; k>=128 -> x vs W_r1.
__global__ __launch_bounds__(256) void gemm1_kernel(
    const float* __restrict__ x,
    const float* __restrict__ Wl1, const float* __restrict__ Wr1,
    const float* __restrict__ b1) {
    __shared__ float As[BK][BM];        // transposed A tile
    __shared__ float Bs[BK][BN + 4];    // transposed B tile (pad: fewer conflicts)
    __shared__ float sinv[BM];

    const int tid  = threadIdx.x;
    const int row0 = blockIdx.x * BM;
    const int jbase = blockIdx.y * BN;  // 0 or 128

    if (tid < BM) {
        int r = row0 + tid;
        float d = (r < N_NODES) ? g_deg[r] : 1.0f;
        sinv[tid] = 1.0f / fmaxf(d, 1.0f);
    }
    __syncthreads();

    float acc[TM][TN];
    #pragma unroll
    for (int m = 0; m < TM; m++)
        #pragma unroll
        for (int n = 0; n < TN; n++) acc[m][n] = 0.f;

    const int trow = tid >> 5;   // 0..7
    const int tcol = tid & 31;   // 0..31

    for (int kc = 0; kc < 256; kc += BK) {
        const bool aggChunk = (kc < 128);
        const int koff = aggChunk ? kc : (kc - 128);
        const float* Abase = aggChunk ? g_agg1 : x;
        const float* Bbase = aggChunk ? Wl1 : Wr1;

        // A tile: 64 rows x 32 k = 512 float4, 2 per thread
        #pragma unroll
        for (int i = 0; i < 2; i++) {
            int lid = tid + i * 256;       // 0..511
            int r   = lid >> 3;            // 0..63
            int g   = lid & 7;             // float4 idx within 32 k
            int grow = row0 + r;
            float4 v = make_float4(0.f, 0.f, 0.f, 0.f);
            if (grow < N_NODES)
                v = *reinterpret_cast<const float4*>(
                        Abase + (size_t)grow * 128 + koff + g * 4);
            float s = aggChunk ? sinv[r] : 1.0f;
            As[g * 4 + 0][r] = v.x * s;
            As[g * 4 + 1][r] = v.y * s;
            As[g * 4 + 2][r] = v.z * s;
            As[g * 4 + 3][r] = v.w * s;
        }
        // B tile: 128 j x 32 k = 1024 float4, 4 per thread
        #pragma unroll
        for (int i = 0; i < 4; i++) {
            int lid = tid + i * 256;       // 0..1023
            int j   = lid >> 3;            // 0..127
            int g   = lid & 7;
            float4 v = *reinterpret_cast<const float4*>(
                        Bbase + (size_t)(jbase + j) * 128 + koff + g * 4);
            Bs[g * 4 + 0][j] = v.x;
            Bs[g * 4 + 1][j] = v.y;
            Bs[g * 4 + 2][j] = v.z;
            Bs[g * 4 + 3][j] = v.w;
        }
        __syncthreads();

        #pragma unroll
        for (int k = 0; k < BK; k++) {
            float a[TM], b[TN];
            #pragma unroll
            for (int m = 0; m < TM; m++) a[m] = As[k][trow * TM + m];
            #pragma unroll
            for (int n = 0; n < TN; n++) b[n] = Bs[k][tcol * TN + n];
            #pragma unroll
            for (int m = 0; m < TM; m++)
                #pragma unroll
                for (int n = 0; n < TN; n++)
                    acc[m][n] = fmaf(a[m], b[n], acc[m][n]);
        }
        __syncthreads();
    }

    // epilogue: h = acc + b1
    const int j0 = jbase + tcol * TN;
    float4 bias = *reinterpret_cast<const float4*>(b1 + j0);
    #pragma unroll
    for (int m = 0; m < TM; m++) {
        int r = row0 + trow * TM + m;
        if (r >= N_NODES) continue;
        float4 o;
        o.x = acc[m][0] + bias.x;
        o.y = acc[m][1] + bias.y;
        o.z = acc[m][2] + bias.z;
        o.w = acc[m][3] + bias.w;
        *reinterpret_cast<float4*>(g_h + (size_t)r * 256 + j0) = o;
    }
}

// Layer 2 projections (one launch, K=256, A = g_h):
//   blockIdx.y==0: g_p  = h @ W_l2^T          (no bias)
//   blockIdx.y==1: out  = h @ W_r2^T + b_l2   (aggregated part added later)
__global__ __launch_bounds__(256) void gemm2_kernel(
    const float* __restrict__ Wl2, const float* __restrict__ Wr2,
    const float* __restrict__ b2, float* __restrict__ out) {
    __shared__ float As[BK][BM];
    __shared__ float Bs[BK][BN + 4];

    const int tid  = threadIdx.x;
    const int row0 = blockIdx.x * BM;
    const bool rpath = (blockIdx.y == 1);
    const float* Bbase = rpath ? Wr2 : Wl2;

    float acc[TM][TN];
    #pragma unroll
    for (int m = 0; m < TM; m++)
        #pragma unroll
        for (int n = 0; n < TN; n++) acc[m][n] = 0.f;

    const int trow = tid >> 5;
    const int tcol = tid & 31;

    for (int kc = 0; kc < 256; kc += BK) {
        #pragma unroll
        for (int i = 0; i < 2; i++) {
            int lid = tid + i * 256;
            int r   = lid >> 3;
            int g   = lid & 7;
            int grow = row0 + r;
            float4 v = make_float4(0.f, 0.f, 0.f, 0.f);
            if (grow < N_NODES)
                v = *reinterpret_cast<const float4*>(
                        g_h + (size_t)grow * 256 + kc + g * 4);
            As[g * 4 + 0][r] = v.x;
            As[g * 4 + 1][r] = v.y;
            As[g * 4 + 2][r] = v.z;
            As[g * 4 + 3][r] = v.w;
        }
        #pragma unroll
        for (int i = 0; i < 4; i++) {
            int lid = tid + i * 256;
            int j   = lid >> 3;            // 0..127 (each weight has 128 rows)
            int g   = lid & 7;
            float4 v = *reinterpret_cast<const float4*>(
                        Bbase + (size_t)j * 256 + kc + g * 4);
            Bs[g * 4 + 0][j] = v.x;
            Bs[g * 4 + 1][j] = v.y;
            Bs[g * 4 + 2][j] = v.z;
            Bs[g * 4 + 3][j] = v.w;
        }
        __syncthreads();

        #pragma unroll
        for (int k = 0; k < BK; k++) {
            float a[TM], b[TN];
            #pragma unroll
            for (int m = 0; m < TM; m++) a[m] = As[k][trow * TM + m];
            #pragma unroll
            for (int n = 0; n < TN; n++) b[n] = Bs[k][tcol * TN + n];
            #pragma unroll
            for (int m = 0; m < TM; m++)
                #pragma unroll
                for (int n = 0; n < TN; n++)
                    acc[m][n] = fmaf(a[m], b[n], acc[m][n]);
        }
        __syncthreads();
    }

    const int j0 = tcol * TN;              // 0..124
    if (rpath) {
        float4 bias = *reinterpret_cast<const float4*>(b2 + j0);
        #pragma unroll
        for (int m = 0; m < TM; m++) {
            int r = row0 + trow * TM + m;
            if (r >= N_NODES) continue;
            float4 o;
            o.x = acc[m][0] + bias.x;
            o.y = acc[m][1] + bias.y;
            o.z = acc[m][2] + bias.z;
            o.w = acc[m][3] + bias.w;
            *reinterpret_cast<float4*>(out + (size_t)r * 128 + j0) = o;
        }
    } else {
        #pragma unroll
        for (int m = 0; m < TM; m++) {
            int r = row0 + trow * TM + m;
            if (r >= N_NODES) continue;
            float4 o = make_float4(acc[m][0], acc[m][1], acc[m][2], acc[m][3]);
            *reinterpret_cast<float4*>(g_p + (size_t)r * 128 + j0) = o;
        }
    }
}

// ---------------- finalize: out += agg2 / max(deg,1) -------------------------
__global__ void finalize_kernel(float* __restrict__ out) {
    int i = blockIdx.x * blockDim.x + threadIdx.x;   // float4 index
    if (i >= N_NODES * (D_OUT / 4)) return;
    int node = i >> 5;                               // 32 float4 per node
    float inv = 1.0f / fmaxf(g_deg[node], 1.0f);
    float4 a = reinterpret_cast<const float4*>(g_agg2)[i];
    float4 o = reinterpret_cast<float4*>(out)[i];
    o.x = fmaf(a.x, inv, o.x);
    o.y = fmaf(a.y, inv, o.y);
    o.z = fmaf(a.z, inv, o.z);
    o.w = fmaf(a.w, inv, o.w);
    reinterpret_cast<float4*>(out)[i] = o;
}

// ---------------- launch ------------------------------------------------------
extern "C" void kernel_launch(void* const* d_in, const int* in_sizes, int n_in,
                              void* d_out, int out_size) {
    const float* x   = (const float*)d_in[0];
    const void*  ei  = d_in[1];                // int32 or int64 — detected on device
    const float* Wl1 = (const float*)d_in[2];
    const float* b1  = (const float*)d_in[3];
    const float* Wr1 = (const float*)d_in[4];
    const float* Wl2 = (const float*)d_in[5];
    const float* b2  = (const float*)d_in[6];
    const float* Wr2 = (const float*)d_in[7];
    float* out = (float*)d_out;

    // 0) detect edge_index dtype (capture-safe, deterministic)
    detect_kernel<<<1, 256>>>((const long long*)ei);
    // 1) zero scratch (deg, agg1, agg2)
    {
        int n = N_NODES * D_IN / 4;   // covers both agg buffers + deg
        zero_kernel<<<(n + 255) / 256, 256>>>();
    }
    // 2) layer-1 aggregation: agg1[dst] += x[src], deg[dst] += 1
    {
        int warps = (N_EDGES + EPW - 1) / EPW;       // 200k warps
        int blocks = (warps * 32 + 255) / 256;
        edge_scatter<1><<<blocks, 256>>>(x, ei);
    }
    // 3) layer-1 fused GEMM -> g_h
    {
        dim3 grid((N_NODES + BM - 1) / BM, 2);
        gemm1_kernel<<<grid, 256>>>(x, Wl1, Wr1, b1);
    }
    // 4) layer-2 projections -> g_p (left path), out = h@Wr2^T + b2 (root path)
    {
        dim3 grid((N_NODES + BM - 1) / BM, 2);
        gemm2_kernel<<<grid, 256>>>(Wl2, Wr2, b2, out);
    }
    // 5) layer-2 aggregation in projected (128-d) space: agg2[dst] += p[src]
    {
        int warps = (N_EDGES + EPW - 1) / EPW;
        int blocks = (warps * 32 + 255) / 256;
        edge_scatter<2><<<blocks, 256>>>(nullptr, ei);
    }
    // 6) out += agg2 / max(deg,1)
    {
        int n = N_NODES * (D_OUT / 4);
        finalize_kernel<<<(n + 255) / 256, 256>>>(out);
    }
}

// round 12
// speedup vs baseline: 1.2822x; 1.2822x over previous
#include <cuda_runtime.h>
#include <cuda_bf16.h>
#include <mma.h>
#include <cstdint>

using namespace nvcuda;

// Problem constants
#define N_NODES 50000
#define N_PAD   50048            // padded to multiple of 128 (full-tile stores)
#define N_EDGES 800000
#define D_IN    128
#define D_HID   256
#define D_OUT   128

// ---------------- scratch (static device globals; no allocation) -------------
// Reference ONLY from device code (GB300 ATS: host-shadow deref is silent).
__device__ int   g_is64;
__device__ float g_deg [N_PAD];
__device__ float g_agg1[(size_t)N_PAD * D_IN];    // sum of x over in-edges
__device__ float g_h   [(size_t)N_PAD * D_HID];   // layer-1 GEMM result (NO bias)
__device__ float g_p   [(size_t)N_PAD * D_OUT];   // h@Wl2^T part (NO c_l)
__device__ float g_r   [(size_t)N_PAD * D_OUT];   // h@Wr2^T part (NO c_r/b2)
__device__ float g_agg2[(size_t)N_PAD * D_OUT];   // sum of g_p over in-edges
__device__ float g_cvec[256];                     // [0:128)=Wl2@b1, [128:256)=Wr2@b1
// Preconverted weights (bf16 hi/lo split), concatenated layouts:
// W1cat[j][k] (256x256): k<128 -> Wl1[j][k], k>=128 -> Wr1[j][k-128]
// W2cat[j][k] (256x256): j<128 -> Wl2[j][k], j>=128 -> Wr2[j-128][k]
__device__ __nv_bfloat16 g_W1hi[256 * 256];
__device__ __nv_bfloat16 g_W1lo[256 * 256];
__device__ __nv_bfloat16 g_W2hi[256 * 256];
__device__ __nv_bfloat16 g_W2lo[256 * 256];

// ---------------- dtype detect (int64 vs int32 edge_index) -------------------
__global__ void detect_kernel(const long long* __restrict__ ei64) {
    __shared__ int bad;
    if (threadIdx.x == 0) bad = 0;
    __syncthreads();
    for (int i = threadIdx.x; i < 4096; i += blockDim.x) {
        long long v = ei64[i];
        if (v < 0 || v >= N_NODES) bad = 1;
    }
    __syncthreads();
    if (threadIdx.x == 0) g_is64 = bad ? 0 : 1;
}

// ---------------- zero scratch ----------------------------------------------
__global__ void zero_kernel() {
    int i = blockIdx.x * blockDim.x + threadIdx.x;
    const int n4a = N_NODES * D_IN  / 4;
    const int n4b = N_NODES * D_OUT / 4;
    float4 z = make_float4(0.f, 0.f, 0.f, 0.f);
    if (i < n4a) reinterpret_cast<float4*>(g_agg1)[i] = z;
    if (i < n4b) reinterpret_cast<float4*>(g_agg2)[i] = z;
    if (i < N_NODES) g_deg[i] = 0.f;
}

// ---------------- edge scatter (proven R7) -----------------------------------
#define EPW 4
template <int PASS>
__global__ __launch_bounds__(256) void edge_scatter(
        const float* __restrict__ xin,
        const void* __restrict__ ei_raw) {
    const int warp  = (blockIdx.x * blockDim.x + threadIdx.x) >> 5;
    const int lane  = threadIdx.x & 31;
    const int ebase = warp * EPW;
    if (ebase >= N_EDGES) return;

    const float* feat = (PASS == 1) ? xin : g_p;
    float*       agg  = (PASS == 1) ? g_agg1 : g_agg2;

    const int is64 = g_is64;
    const int*       ei32 = (const int*)ei_raw;
    const long long* ei64 = (const long long*)ei_raw;

    #pragma unroll
    for (int q = 0; q < EPW; q++) {
        int e = ebase + q;
        if (e >= N_EDGES) break;
        int src, dst;
        if (is64) {
            src = (int)__ldg(&ei64[e]);
            dst = (int)__ldg(&ei64[N_EDGES + e]);
        } else {
            src = __ldg(&ei32[e]);
            dst = __ldg(&ei32[N_EDGES + e]);
        }
        float4 v = __ldg(reinterpret_cast<const float4*>(
                             feat + (size_t)src * 128) + lane);
        float* p = agg + (size_t)dst * 128 + lane * 4;
        asm volatile("red.global.add.v4.f32 [%0], {%1,%2,%3,%4};"
                     :: "l"(p), "f"(v.x), "f"(v.y), "f"(v.z), "f"(v.w)
                     : "memory");
        if (PASS == 1 && lane == 0) {
            asm volatile("red.global.add.f32 [%0], %1;"
                         :: "l"(&g_deg[dst]), "f"(1.0f) : "memory");
        }
    }
}

// ---------------- weight preconvert: fp32 -> bf16 hi/lo concat tables --------
__global__ void preconvert_kernel(const float* __restrict__ Wl1,
                                  const float* __restrict__ Wr1,
                                  const float* __restrict__ Wl2,
                                  const float* __restrict__ Wr2) {
    int idx = blockIdx.x * blockDim.x + threadIdx.x;   // 0..65535
    if (idx >= 256 * 256) return;
    int j = idx >> 8, k = idx & 255;
    {
        float v = (k < 128) ? Wl1[j * 128 + k] : Wr1[j * 128 + (k - 128)];
        __nv_bfloat16 h = __float2bfloat16(v);
        __nv_bfloat16 l = __float2bfloat16(v - __bfloat162float(h));
        g_W1hi[idx] = h; g_W1lo[idx] = l;
    }
    {
        float v = (j < 128) ? Wl2[j * 256 + k] : Wr2[(j - 128) * 256 + k];
        __nv_bfloat16 h = __float2bfloat16(v);
        __nv_bfloat16 l = __float2bfloat16(v - __bfloat162float(h));
        g_W2hi[idx] = h; g_W2lo[idx] = l;
    }
}

// ---------------- bias fold: g_cvec = W2cat @ b1 -----------------------------
__global__ void cvec_kernel(const float* __restrict__ Wl2,
                            const float* __restrict__ Wr2,
                            const float* __restrict__ b1) {
    int j = threadIdx.x;                 // 256 threads, one output each
    const float* w = (j < 128) ? (Wl2 + (size_t)j * 256)
                               : (Wr2 + (size_t)(j - 128) * 256);
    float s = 0.f;
    #pragma unroll 8
    for (int k = 0; k < 256; k++) s = fmaf(w[k], b1[k], s);
    g_cvec[j] = s;
}

// ---------------- HMMA (wmma) GEMM: D[128x256] = A[128x256] @ Wcat^T ---------
// bf16-split: D = A_hi*B_hi + A_hi*B_lo + A_lo*B_hi, fp32 accumulators.
// PASS 1: A = [agg1/deg | x], B = W1cat, store -> g_h (no bias)
// PASS 2: A = g_h, B = W2cat, jbase 0 -> g_p, jbase 128 -> g_r (no bias)
#define BM 128
#define BN 128
#define BK 32
#define BKP 40      // padded ld (elements); 80B row stride, 16B aligned

template <int PASS>
__global__ __launch_bounds__(256) void mma_gemm(const float* __restrict__ xin) {
    // __align__(16): uint4/vector stores below require 16B base alignment,
    // which bf16 shared arrays do not otherwise guarantee.
    __shared__ __align__(16) __nv_bfloat16 Ahi[BM][BKP], Alo[BM][BKP];
    __shared__ __align__(16) __nv_bfloat16 Bhi[BN][BKP], Blo[BN][BKP];
    __shared__ float sinv[BM];

    const int tid   = threadIdx.x;
    const int wid   = tid >> 5;
    const int row0  = blockIdx.x * BM;
    const int jbase = blockIdx.y * BN;
    const int warp_m = wid >> 2;   // 0..1 -> 64-row slab
    const int warp_n = wid & 3;    // 0..3 -> 32-col slab

    if (PASS == 1 && tid < BM) {
        int r = row0 + tid;
        float d = (r < N_NODES) ? g_deg[r] : 1.0f;
        sinv[tid] = 1.0f / fmaxf(d, 1.0f);
    }
    __syncthreads();

    wmma::fragment<wmma::accumulator, 16, 16, 16, float> acc[4][2];
    #pragma unroll
    for (int m = 0; m < 4; m++)
        #pragma unroll
        for (int n = 0; n < 2; n++) wmma::fill_fragment(acc[m][n], 0.0f);

    const __nv_bfloat16* Whi = (PASS == 1) ? g_W1hi : g_W2hi;
    const __nv_bfloat16* Wlo = (PASS == 1) ? g_W1lo : g_W2lo;

    for (int ck = 0; ck < 8; ck++) {
        const int kc = ck * BK;

        // ---- A tile: 128 rows x 32 k fp32 -> bf16 hi/lo (1024 float4) ----
        #pragma unroll
        for (int ii = 0; ii < 4; ii++) {
            int i = tid + ii * 256;
            int r = i >> 3, q = i & 7;
            int row = row0 + r;
            float4 v = make_float4(0.f, 0.f, 0.f, 0.f);
            float s = 1.0f;
            if (PASS == 1) {
                if (kc < 128) {
                    // g_agg1 padded to N_PAD; OOB rows zero-init, never written
                    v = *reinterpret_cast<const float4*>(
                            g_agg1 + (size_t)row * 128 + kc + q * 4);
                    s = sinv[r];
                } else if (row < N_NODES) {       // x is harness buffer: guard!
                    v = *reinterpret_cast<const float4*>(
                            xin + (size_t)row * 128 + (kc - 128) + q * 4);
                }
            } else {
                v = *reinterpret_cast<const float4*>(
                        g_h + (size_t)row * 256 + kc + q * 4);   // padded
            }
            float a0 = v.x * s, a1 = v.y * s, a2 = v.z * s, a3 = v.w * s;
            __nv_bfloat16 h0 = __float2bfloat16(a0), h1 = __float2bfloat16(a1);
            __nv_bfloat16 h2 = __float2bfloat16(a2), h3 = __float2bfloat16(a3);
            __nv_bfloat16 l0 = __float2bfloat16(a0 - __bfloat162float(h0));
            __nv_bfloat16 l1 = __float2bfloat16(a1 - __bfloat162float(h1));
            __nv_bfloat16 l2 = __float2bfloat16(a2 - __bfloat162float(h2));
            __nv_bfloat16 l3 = __float2bfloat16(a3 - __bfloat162float(h3));
            *reinterpret_cast<__nv_bfloat162*>(&Ahi[r][q * 4 + 0]) =
                __halves2bfloat162(h0, h1);
            *reinterpret_cast<__nv_bfloat162*>(&Ahi[r][q * 4 + 2]) =
                __halves2bfloat162(h2, h3);
            *reinterpret_cast<__nv_bfloat162*>(&Alo[r][q * 4 + 0]) =
                __halves2bfloat162(l0, l1);
            *reinterpret_cast<__nv_bfloat162*>(&Alo[r][q * 4 + 2]) =
                __halves2bfloat162(l2, l3);
        }
        // ---- B tile: 128 rows x 32 k bf16 (preconverted), 512 uint4 ----
        #pragma unroll
        for (int ii = 0; ii < 2; ii++) {
            int i = tid + ii * 256;
            int r = i >> 2, q = i & 3;
            const uint4* sh =
                reinterpret_cast<const uint4*>(Whi + (size_t)(jbase + r) * 256 + kc) + q;
            const uint4* sl =
                reinterpret_cast<const uint4*>(Wlo + (size_t)(jbase + r) * 256 + kc) + q;
            *reinterpret_cast<uint4*>(&Bhi[r][q * 8]) = *sh;
            *reinterpret_cast<uint4*>(&Blo[r][q * 8]) = *sl;
        }
        __syncthreads();

        // ---- compute: 2 k-steps of 16 ----
        #pragma unroll
        for (int ks = 0; ks < 2; ks++) {
            const int k0 = ks * 16;
            wmma::fragment<wmma::matrix_b, 16, 16, 16, __nv_bfloat16,
                           wmma::col_major> bh[2], bl[2];
            #pragma unroll
            for (int n = 0; n < 2; n++) {
                wmma::load_matrix_sync(bh[n], &Bhi[warp_n * 32 + n * 16][k0], BKP);
                wmma::load_matrix_sync(bl[n], &Blo[warp_n * 32 + n * 16][k0], BKP);
            }
            #pragma unroll
            for (int m = 0; m < 4; m++) {
                wmma::fragment<wmma::matrix_a, 16, 16, 16, __nv_bfloat16,
                               wmma::row_major> ah, al;
                wmma::load_matrix_sync(ah, &Ahi[warp_m * 64 + m * 16][k0], BKP);
                wmma::load_matrix_sync(al, &Alo[warp_m * 64 + m * 16][k0], BKP);
                #pragma unroll
                for (int n = 0; n < 2; n++) {
                    wmma::mma_sync(acc[m][n], ah, bh[n], acc[m][n]);
                    wmma::mma_sync(acc[m][n], ah, bl[n], acc[m][n]);
                    wmma::mma_sync(acc[m][n], al, bh[n], acc[m][n]);
                }
            }
        }
        __syncthreads();
    }

    // ---- store (scratch is padded; no bias — folded into finalize) ----
    #pragma unroll
    for (int m = 0; m < 4; m++) {
        int row = row0 + warp_m * 64 + m * 16;
        #pragma unroll
        for (int n = 0; n < 2; n++) {
            int col = warp_n * 32 + n * 16;
            if (PASS == 1) {
                wmma::store_matrix_sync(g_h + (size_t)row * 256 + jbase + col,
                                        acc[m][n], 256, wmma::mem_row_major);
            } else {
                float* dst = (blockIdx.y == 0) ? g_p : g_r;
                wmma::store_matrix_sync(dst + (size_t)row * 128 + col,
                                        acc[m][n], 128, wmma::mem_row_major);
            }
        }
    }
}

// ---------------- finalize ----------------------------------------------------
// out = g_r + b2 + c_r + agg2/max(deg,1) + (deg>0) * c_l
__global__ void finalize_kernel(const float* __restrict__ b2,
                                float* __restrict__ out) {
    int i = blockIdx.x * blockDim.x + threadIdx.x;   // float4 index
    if (i >= N_NODES * (D_OUT / 4)) return;
    int node = i >> 5;
    int t4 = (i & 31) * 4;
    float deg = g_deg[node];
    float inv = 1.0f / fmaxf(deg, 1.0f);
    float has = (deg > 0.f) ? 1.0f : 0.0f;
    float4 r  = reinterpret_cast<const float4*>(g_r)[i];
    float4 a  = reinterpret_cast<const float4*>(g_agg2)[i];
    float4 cl = *reinterpret_cast<const float4*>(g_cvec + t4);
    float4 cr = *reinterpret_cast<const float4*>(g_cvec + 128 + t4);
    float4 bb = *reinterpret_cast<const float4*>(b2 + t4);
    float4 o;
    o.x = r.x + bb.x + cr.x + a.x * inv + has * cl.x;
    o.y = r.y + bb.y + cr.y + a.y * inv + has * cl.y;
    o.z = r.z + bb.z + cr.z + a.z * inv + has * cl.z;
    o.w = r.w + bb.w + cr.w + a.w * inv + has * cl.w;
    reinterpret_cast<float4*>(out)[i] = o;
}

// ---------------- launch ------------------------------------------------------
extern "C" void kernel_launch(void* const* d_in, const int* in_sizes, int n_in,
                              void* d_out, int out_size) {
    const float* x   = (const float*)d_in[0];
    const void*  ei  = d_in[1];
    const float* Wl1 = (const float*)d_in[2];
    const float* b1  = (const float*)d_in[3];
    const float* Wr1 = (const float*)d_in[4];
    const float* Wl2 = (const float*)d_in[5];
    const float* b2  = (const float*)d_in[6];
    const float* Wr2 = (const float*)d_in[7];
    float* out = (float*)d_out;

    // 0) dtype detect + zero scratch + weight preconvert + bias fold
    detect_kernel<<<1, 256>>>((const long long*)ei);
    {
        int n = N_NODES * D_IN / 4;
        zero_kernel<<<(n + 255) / 256, 256>>>();
    }
    preconvert_kernel<<<256, 256>>>(Wl1, Wr1, Wl2, Wr2);
    cvec_kernel<<<1, 256>>>(Wl2, Wr2, b1);
    // 1) layer-1 aggregation: agg1[dst] += x[src], deg[dst] += 1
    {
        int warps = (N_EDGES + EPW - 1) / EPW;
        int blocks = (warps * 32 + 255) / 256;
        edge_scatter<1><<<blocks, 256>>>(x, ei);
    }
    // 2) layer-1 HMMA GEMM -> g_h
    {
        dim3 grid(N_PAD / BM, 2);
        mma_gemm<1><<<grid, 256>>>(x);
    }
    // 3) layer-2 HMMA GEMM -> g_p (jbase 0), g_r (jbase 128)
    {
        dim3 grid(N_PAD / BM, 2);
        mma_gemm<2><<<grid, 256>>>(nullptr);
    }
    // 4) layer-2 aggregation: agg2[dst] += g_p[src]
    {
        int warps = (N_EDGES + EPW - 1) / EPW;
        int blocks = (warps * 32 + 255) / 256;
        edge_scatter<2><<<blocks, 256>>>(nullptr, ei);
    }
    // 5) compose output
    {
        int n = N_NODES * (D_OUT / 4);
        finalize_kernel<<<(n + 255) / 256, 256>>>(b2, out);
    }
}

// round 16
// speedup vs baseline: 1.7516x; 1.3661x over previous
#include <cuda_runtime.h>
#include <cuda_bf16.h>
#include <mma.h>
#include <cstdint>

using namespace nvcuda;

// Problem constants
#define N_NODES 50000
#define N_PAD   50048            // padded to multiple of 128 (full-tile stores)
#define N_EDGES 800000
#define D_IN    128
#define D_HID   256
#define D_OUT   128

// ---------------- scratch (static device globals; no allocation) -------------
// Reference ONLY from device code (GB300 ATS: host-shadow deref is silent).
__device__ int   g_is64;
__device__ int   g_cnt [N_NODES];                 // in-degree counts
__device__ int   g_off [N_NODES + 1];             // CSR offsets
__device__ int   g_cur [N_NODES];                 // fill cursors
__device__ int   g_csrc[N_EDGES];                 // CSR: src per (dst-grouped) slot
__device__ int   g_bsum[256];                     // scan partials
__device__ float g_agg1[(size_t)N_PAD * D_IN];    // MEAN of x over in-edges
__device__ float g_h   [(size_t)N_PAD * D_HID];   // layer-1 GEMM result (NO bias)
__device__ float g_p   [(size_t)N_PAD * D_OUT];   // h@Wl2^T part (NO c_l)
__device__ float g_r   [(size_t)N_PAD * D_OUT];   // h@Wr2^T part (NO c_r/b2)
__device__ float g_agg2[(size_t)N_PAD * D_OUT];   // MEAN of g_p over in-edges
__device__ float g_cvec[256];                     // [0:128)=Wl2@b1, [128:256)=Wr2@b1
// Preconverted weights (bf16 hi/lo split), concatenated layouts:
// W1cat[j][k] (256x256): k<128 -> Wl1[j][k], k>=128 -> Wr1[j][k-128]
// W2cat[j][k] (256x256): j<128 -> Wl2[j][k], j>=128 -> Wr2[j-128][k]
__device__ __nv_bfloat16 g_W1hi[256 * 256];
__device__ __nv_bfloat16 g_W1lo[256 * 256];
__device__ __nv_bfloat16 g_W2hi[256 * 256];
__device__ __nv_bfloat16 g_W2lo[256 * 256];

// ---------------- dtype detect (int64 vs int32 edge_index) -------------------
__global__ void detect_kernel(const long long* __restrict__ ei64) {
    __shared__ int bad;
    if (threadIdx.x == 0) bad = 0;
    __syncthreads();
    for (int i = threadIdx.x; i < 4096; i += blockDim.x) {
        long long v = ei64[i];
        if (v < 0 || v >= N_NODES) bad = 1;
    }
    __syncthreads();
    if (threadIdx.x == 0) g_is64 = bad ? 0 : 1;
}

__device__ __forceinline__ int load_idx(const void* ei_raw, int pos, int is64) {
    return is64 ? (int)__ldg(&((const long long*)ei_raw)[pos])
                : __ldg(&((const int*)ei_raw)[pos]);
}

// ---------------- CSR build ---------------------------------------------------
__global__ void zero_cnt_kernel() {
    int i = blockIdx.x * blockDim.x + threadIdx.x;
    if (i < N_NODES) g_cnt[i] = 0;
}

__global__ void hist_kernel(const void* __restrict__ ei_raw) {
    int e = blockIdx.x * blockDim.x + threadIdx.x;
    if (e >= N_EDGES) return;
    int dst = load_idx(ei_raw, N_EDGES + e, g_is64);
    atomicAdd(&g_cnt[dst], 1);
}

#define SCAN_CHUNK 196   // 196 * 256 blocks = 50176 >= N_NODES
__global__ void scan1_kernel() {           // per-block partial sums
    __shared__ int sh[256];
    int t = threadIdx.x;
    int idx = blockIdx.x * SCAN_CHUNK + t;
    int v = (t < SCAN_CHUNK && idx < N_NODES) ? g_cnt[idx] : 0;
    sh[t] = v;
    __syncthreads();
    for (int d = 128; d > 0; d >>= 1) {
        if (t < d) sh[t] += sh[t + d];
        __syncthreads();
    }
    if (t == 0) g_bsum[blockIdx.x] = sh[0];
}

__global__ void scan2_kernel() {           // inclusive scan of 256 partials
    __shared__ int sh[256];
    int t = threadIdx.x;
    sh[t] = g_bsum[t];
    __syncthreads();
    for (int d = 1; d < 256; d <<= 1) {    // Hillis-Steele inclusive
        int x = (t >= d) ? sh[t - d] : 0;
        __syncthreads();
        sh[t] += x;
        __syncthreads();
    }
    g_bsum[t] = sh[t];                     // INCLUSIVE; scan3 uses [b-1] as base
    if (t == 0) g_off[N_NODES] = N_EDGES;
}

__global__ void scan3_kernel() {           // final offsets
    __shared__ int sh[256];
    int t = threadIdx.x;
    int b = blockIdx.x;
    int idx = b * SCAN_CHUNK + t;
    int v = (t < SCAN_CHUNK && idx < N_NODES) ? g_cnt[idx] : 0;
    sh[t] = v;
    __syncthreads();
    for (int d = 1; d < 256; d <<= 1) {    // inclusive scan
        int x = (t >= d) ? sh[t - d] : 0;
        __syncthreads();
        sh[t] += x;
        __syncthreads();
    }
    int base = (b == 0) ? 0 : g_bsum[b - 1];
    if (t < SCAN_CHUNK && idx < N_NODES) {
        g_off[idx] = base + sh[t] - v;     // exclusive
        g_cur[idx] = base + sh[t] - v;     // fill cursor starts at offset
    }
}

__global__ void fill_kernel(const void* __restrict__ ei_raw) {
    int e = blockIdx.x * blockDim.x + threadIdx.x;
    if (e >= N_EDGES) return;
    int is64 = g_is64;
    int src = load_idx(ei_raw, e, is64);
    int dst = load_idx(ei_raw, N_EDGES + e, is64);
    int slot = atomicAdd(&g_cur[dst], 1);
    g_csrc[slot] = src;
}

// ---------------- CSR gather: agg[v] = mean_{e in N(v)} feat[src_e] ----------
// One warp per node; lane handles one float4 (32*4 = 128 floats).
// PASS 1: feat = x (kernel arg) -> g_agg1. PASS 2: feat = g_p -> g_agg2.
template <int PASS>
__global__ __launch_bounds__(256) void gather_kernel(
        const float* __restrict__ xin) {
    const int warp = (blockIdx.x * blockDim.x + threadIdx.x) >> 5;
    const int lane = threadIdx.x & 31;
    if (warp >= N_NODES) return;

    const float* feat = (PASS == 1) ? xin : g_p;
    float*       agg  = (PASS == 1) ? g_agg1 : g_agg2;

    const int beg = g_off[warp];
    const int end = g_off[warp + 1];

    float4 acc = make_float4(0.f, 0.f, 0.f, 0.f);
    int e = beg;
    for (; e + 1 < end; e += 2) {          // MLP=2
        int s0 = __ldg(&g_csrc[e]);
        int s1 = __ldg(&g_csrc[e + 1]);
        float4 v0 = __ldg(reinterpret_cast<const float4*>(
                              feat + (size_t)s0 * 128) + lane);
        float4 v1 = __ldg(reinterpret_cast<const float4*>(
                              feat + (size_t)s1 * 128) + lane);
        acc.x += v0.x + v1.x; acc.y += v0.y + v1.y;
        acc.z += v0.z + v1.z; acc.w += v0.w + v1.w;
    }
    if (e < end) {
        int s0 = __ldg(&g_csrc[e]);
        float4 v0 = __ldg(reinterpret_cast<const float4*>(
                              feat + (size_t)s0 * 128) + lane);
        acc.x += v0.x; acc.y += v0.y; acc.z += v0.z; acc.w += v0.w;
    }
    int deg = end - beg;
    float inv = 1.0f / (float)max(deg, 1);
    acc.x *= inv; acc.y *= inv; acc.z *= inv; acc.w *= inv;
    reinterpret_cast<float4*>(agg + (size_t)warp * 128)[lane] = acc;
}

// ---------------- weight preconvert: fp32 -> bf16 hi/lo concat tables --------
__global__ void preconvert_kernel(const float* __restrict__ Wl1,
                                  const float* __restrict__ Wr1,
                                  const float* __restrict__ Wl2,
                                  const float* __restrict__ Wr2) {
    int idx = blockIdx.x * blockDim.x + threadIdx.x;   // 0..65535
    if (idx >= 256 * 256) return;
    int j = idx >> 8, k = idx & 255;
    {
        float v = (k < 128) ? Wl1[j * 128 + k] : Wr1[j * 128 + (k - 128)];
        __nv_bfloat16 h = __float2bfloat16(v);
        __nv_bfloat16 l = __float2bfloat16(v - __bfloat162float(h));
        g_W1hi[idx] = h; g_W1lo[idx] = l;
    }
    {
        float v = (j < 128) ? Wl2[j * 256 + k] : Wr2[(j - 128) * 256 + k];
        __nv_bfloat16 h = __float2bfloat16(v);
        __nv_bfloat16 l = __float2bfloat16(v - __bfloat162float(h));
        g_W2hi[idx] = h; g_W2lo[idx] = l;
    }
}

// ---------------- bias fold: g_cvec = W2cat @ b1 (parallel: 1 block per j) ---
__global__ void cvec_kernel(const float* __restrict__ Wl2,
                            const float* __restrict__ Wr2,
                            const float* __restrict__ b1) {
    __shared__ float red[4];
    int j = blockIdx.x;                  // 0..255
    int t = threadIdx.x;                 // 0..127
    const float* w = (j < 128) ? (Wl2 + (size_t)j * 256)
                               : (Wr2 + (size_t)(j - 128) * 256);
    float s = fmaf(w[t], b1[t], w[t + 128] * b1[t + 128]);
    #pragma unroll
    for (int d = 16; d > 0; d >>= 1)
        s += __shfl_down_sync(0xFFFFFFFF, s, d);
    if ((t & 31) == 0) red[t >> 5] = s;
    __syncthreads();
    if (t == 0) g_cvec[j] = red[0] + red[1] + red[2] + red[3];
}

// ---------------- HMMA (wmma) GEMM: D[128x256] = A[128x256] @ Wcat^T ---------
// bf16-split: D = A_hi*B_hi + A_hi*B_lo + A_lo*B_hi, fp32 accumulators.
// PASS 1: A = [agg1 (already mean) | x], B = W1cat, store -> g_h (no bias)
// PASS 2: A = g_h, B = W2cat, jbase 0 -> g_p, jbase 128 -> g_r (no bias)
#define BM 128
#define BN 128
#define BK 32
#define BKP 40      // padded ld (elements); 80B row stride, 16B aligned

template <int PASS>
__global__ __launch_bounds__(256) void mma_gemm(const float* __restrict__ xin) {
    // __align__(16): uint4/vector stores below require 16B base alignment.
    __shared__ __align__(16) __nv_bfloat16 Ahi[BM][BKP], Alo[BM][BKP];
    __shared__ __align__(16) __nv_bfloat16 Bhi[BN][BKP], Blo[BN][BKP];

    const int tid   = threadIdx.x;
    const int wid   = tid >> 5;
    const int row0  = blockIdx.x * BM;
    const int jbase = blockIdx.y * BN;
    const int warp_m = wid >> 2;   // 0..1 -> 64-row slab
    const int warp_n = wid & 3;    // 0..3 -> 32-col slab

    wmma::fragment<wmma::accumulator, 16, 16, 16, float> acc[4][2];
    #pragma unroll
    for (int m = 0; m < 4; m++)
        #pragma unroll
        for (int n = 0; n < 2; n++) wmma::fill_fragment(acc[m][n], 0.0f);

    const __nv_bfloat16* Whi = (PASS == 1) ? g_W1hi : g_W2hi;
    const __nv_bfloat16* Wlo = (PASS == 1) ? g_W1lo : g_W2lo;

    for (int ck = 0; ck < 8; ck++) {
        const int kc = ck * BK;

        // ---- A tile: 128 rows x 32 k fp32 -> bf16 hi/lo (1024 float4) ----
        #pragma unroll
        for (int ii = 0; ii < 4; ii++) {
            int i = tid + ii * 256;
            int r = i >> 3, q = i & 7;
            int row = row0 + r;
            float4 v = make_float4(0.f, 0.f, 0.f, 0.f);
            if (PASS == 1) {
                if (kc < 128) {
                    // g_agg1 padded to N_PAD; OOB rows zero-init, never written
                    v = *reinterpret_cast<const float4*>(
                            g_agg1 + (size_t)row * 128 + kc + q * 4);
                } else if (row < N_NODES) {       // x is harness buffer: guard!
                    v = *reinterpret_cast<const float4*>(
                            xin + (size_t)row * 128 + (kc - 128) + q * 4);
                }
            } else {
                v = *reinterpret_cast<const float4*>(
                        g_h + (size_t)row * 256 + kc + q * 4);   // padded
            }
            float a0 = v.x, a1 = v.y, a2 = v.z, a3 = v.w;
            __nv_bfloat16 h0 = __float2bfloat16(a0), h1 = __float2bfloat16(a1);
            __nv_bfloat16 h2 = __float2bfloat16(a2), h3 = __float2bfloat16(a3);
            __nv_bfloat16 l0 = __float2bfloat16(a0 - __bfloat162float(h0));
            __nv_bfloat16 l1 = __float2bfloat16(a1 - __bfloat162float(h1));
            __nv_bfloat16 l2 = __float2bfloat16(a2 - __bfloat162float(h2));
            __nv_bfloat16 l3 = __float2bfloat16(a3 - __bfloat162float(h3));
            *reinterpret_cast<__nv_bfloat162*>(&Ahi[r][q * 4 + 0]) =
                __halves2bfloat162(h0, h1);
            *reinterpret_cast<__nv_bfloat162*>(&Ahi[r][q * 4 + 2]) =
                __halves2bfloat162(h2, h3);
            *reinterpret_cast<__nv_bfloat162*>(&Alo[r][q * 4 + 0]) =
                __halves2bfloat162(l0, l1);
            *reinterpret_cast<__nv_bfloat162*>(&Alo[r][q * 4 + 2]) =
                __halves2bfloat162(l2, l3);
        }
        // ---- B tile: 128 rows x 32 k bf16 (preconverted), 512 uint4 ----
        #pragma unroll
        for (int ii = 0; ii < 2; ii++) {
            int i = tid + ii * 256;
            int r = i >> 2, q = i & 3;
            const uint4* sh =
                reinterpret_cast<const uint4*>(Whi + (size_t)(jbase + r) * 256 + kc) + q;
            const uint4* sl =
                reinterpret_cast<const uint4*>(Wlo + (size_t)(jbase + r) * 256 + kc) + q;
            *reinterpret_cast<uint4*>(&Bhi[r][q * 8]) = *sh;
            *reinterpret_cast<uint4*>(&Blo[r][q * 8]) = *sl;
        }
        __syncthreads();

        // ---- compute: 2 k-steps of 16 ----
        #pragma unroll
        for (int ks = 0; ks < 2; ks++) {
            const int k0 = ks * 16;
            wmma::fragment<wmma::matrix_b, 16, 16, 16, __nv_bfloat16,
                           wmma::col_major> bh[2], bl[2];
            #pragma unroll
            for (int n = 0; n < 2; n++) {
                wmma::load_matrix_sync(bh[n], &Bhi[warp_n * 32 + n * 16][k0], BKP);
                wmma::load_matrix_sync(bl[n], &Blo[warp_n * 32 + n * 16][k0], BKP);
            }
            #pragma unroll
            for (int m = 0; m < 4; m++) {
                wmma::fragment<wmma::matrix_a, 16, 16, 16, __nv_bfloat16,
                               wmma::row_major> ah, al;
                wmma::load_matrix_sync(ah, &Ahi[warp_m * 64 + m * 16][k0], BKP);
                wmma::load_matrix_sync(al, &Alo[warp_m * 64 + m * 16][k0], BKP);
                #pragma unroll
                for (int n = 0; n < 2; n++) {
                    wmma::mma_sync(acc[m][n], ah, bh[n], acc[m][n]);
                    wmma::mma_sync(acc[m][n], ah, bl[n], acc[m][n]);
                    wmma::mma_sync(acc[m][n], al, bh[n], acc[m][n]);
                }
            }
        }
        __syncthreads();
    }

    // ---- store (scratch is padded; no bias — folded into finalize) ----
    #pragma unroll
    for (int m = 0; m < 4; m++) {
        int row = row0 + warp_m * 64 + m * 16;
        #pragma unroll
        for (int n = 0; n < 2; n++) {
            int col = warp_n * 32 + n * 16;
            if (PASS == 1) {
                wmma::store_matrix_sync(g_h + (size_t)row * 256 + jbase + col,
                                        acc[m][n], 256, wmma::mem_row_major);
            } else {
                float* dst = (blockIdx.y == 0) ? g_p : g_r;
                wmma::store_matrix_sync(dst + (size_t)row * 128 + col,
                                        acc[m][n], 128, wmma::mem_row_major);
            }
        }
    }
}

// ---------------- finalize ----------------------------------------------------
// out = g_r + b2 + c_r + agg2 (already mean) + (deg>0) * c_l
__global__ void finalize_kernel(const float* __restrict__ b2,
                                float* __restrict__ out) {
    int i = blockIdx.x * blockDim.x + threadIdx.x;   // float4 index
    if (i >= N_NODES * (D_OUT / 4)) return;
    int node = i >> 5;
    int t4 = (i & 31) * 4;
    float has = (g_cnt[node] > 0) ? 1.0f : 0.0f;
    float4 r  = reinterpret_cast<const float4*>(g_r)[i];
    float4 a  = reinterpret_cast<const float4*>(g_agg2)[i];
    float4 cl = *reinterpret_cast<const float4*>(g_cvec + t4);
    float4 cr = *reinterpret_cast<const float4*>(g_cvec + 128 + t4);
    float4 bb = *reinterpret_cast<const float4*>(b2 + t4);
    float4 o;
    o.x = r.x + bb.x + cr.x + a.x + has * cl.x;
    o.y = r.y + bb.y + cr.y + a.y + has * cl.y;
    o.z = r.z + bb.z + cr.z + a.z + has * cl.z;
    o.w = r.w + bb.w + cr.w + a.w + has * cl.w;
    reinterpret_cast<float4*>(out)[i] = o;
}

// ---------------- launch ------------------------------------------------------
extern "C" void kernel_launch(void* const* d_in, const int* in_sizes, int n_in,
                              void* d_out, int out_size) {
    const float* x   = (const float*)d_in[0];
    const void*  ei  = d_in[1];
    const float* Wl1 = (const float*)d_in[2];
    const float* b1  = (const float*)d_in[3];
    const float* Wr1 = (const float*)d_in[4];
    const float* Wl2 = (const float*)d_in[5];
    const float* b2  = (const float*)d_in[6];
    const float* Wr2 = (const float*)d_in[7];
    float* out = (float*)d_out;

    // 0) dtype detect + CSR build + weight preconvert + bias fold
    detect_kernel<<<1, 256>>>((const long long*)ei);
    zero_cnt_kernel<<<(N_NODES + 255) / 256, 256>>>();
    hist_kernel<<<(N_EDGES + 255) / 256, 256>>>(ei);
    scan1_kernel<<<256, 256>>>();
    scan2_kernel<<<1, 256>>>();
    scan3_kernel<<<256, 256>>>();
    fill_kernel<<<(N_EDGES + 255) / 256, 256>>>(ei);
    preconvert_kernel<<<256, 256>>>(Wl1, Wr1, Wl2, Wr2);
    cvec_kernel<<<256, 128>>>(Wl2, Wr2, b1);
    // 1) layer-1 aggregation (CSR gather, normalized): g_agg1 = mean x[nbrs]
    gather_kernel<1><<<(N_NODES * 32 + 255) / 256, 256>>>(x);
    // 2) layer-1 HMMA GEMM -> g_h
    {
        dim3 grid(N_PAD / BM, 2);
        mma_gemm<1><<<grid, 256>>>(x);
    }
    // 3) layer-2 HMMA GEMM -> g_p (jbase 0), g_r (jbase 128)
    {
        dim3 grid(N_PAD / BM, 2);
        mma_gemm<2><<<grid, 256>>>(nullptr);
    }
    // 4) layer-2 aggregation: g_agg2 = mean g_p[nbrs]
    gather_kernel<2><<<(N_NODES * 32 + 255) / 256, 256>>>(nullptr);
    // 5) compose output
    {
        int n = N_NODES * (D_OUT / 4);
        finalize_kernel<<<(n + 255) / 256, 256>>>(b2, out);
    }
}